// round 2
// baseline (speedup 1.0000x reference)
#include <cuda_runtime.h>
#include <cuda_bf16.h>

// SNDE: stabilized neural ODE, Euler rollout.
//   per step: f = tanh(u@W1+b1)@W2+b2
//             g = tanh(u.wg+bg); G = (1-g^2)*wg; s=|G|^2
//             stable = GAMMA * g/s * G  (0 if s<=EPS)
//             u += dt*(f - stable)
// BS=4096, DIM=64, HID=256, T=101. Rows independent -> persistent CTAs,
// 32 rows/CTA, weights in SMEM, no grid sync.

#define DIMN    64
#define HIDN    256
#define RPB     32      // rows per block
#define NTHR    256
#define UT_STRIDE 36    // padded (16B-aligned vector rows, conflict-free stores)
#define HT_STRIDE 36
#define GAMMA_C 0.1f
#define EPS_C   1e-12f

// smem layout (floats)
#define OFF_W1   0
#define OFF_W2   (OFF_W1 + DIMN*HIDN)          // 16384
#define OFF_HT   (OFF_W2 + HIDN*DIMN)          // 32768
#define OFF_UT   (OFF_HT + HIDN*HT_STRIDE)     // 41984
#define OFF_B1   (OFF_UT + DIMN*UT_STRIDE)     // 44288
#define OFF_B2   (OFF_B1 + HIDN)
#define OFF_WG   (OFF_B2 + DIMN)
#define OFF_COEF (OFF_WG + DIMN)
#define SMEM_FLOATS (OFF_COEF + RPB)
#define SMEM_BYTES  (SMEM_FLOATS * 4)

__device__ __forceinline__ float fast_tanh(float x) {
    // accurate enough (abs err ~1e-7); clamp avoids exp overflow -> NaN
    x = fminf(fmaxf(x, -15.0f), 15.0f);
    float e = __expf(2.0f * x);
    return __fdividef(e - 1.0f, e + 1.0f);
}

__global__ __launch_bounds__(NTHR, 1)
void snde_kernel(const float* __restrict__ y0, const float* __restrict__ t,
                 const float* __restrict__ W1, const float* __restrict__ b1,
                 const float* __restrict__ W2, const float* __restrict__ b2,
                 const float* __restrict__ wg, const float* __restrict__ bg,
                 float* __restrict__ out, int T, int BS)
{
    extern __shared__ float sm[];
    float* W1s  = sm + OFF_W1;   // [64][256]
    float* W2s  = sm + OFF_W2;   // [256][64]
    float* hT   = sm + OFF_HT;   // [256][36] (cols 0..31 used = rows)
    float* uT   = sm + OFF_UT;   // [64][36]  (cols 0..31 used = rows)
    float* b1s  = sm + OFF_B1;
    float* b2s  = sm + OFF_B2;
    float* wgs  = sm + OFF_WG;
    float* coef = sm + OFF_COEF; // [32] per-row stabilizer coefficient

    const int tid  = threadIdx.x;
    const int row0 = blockIdx.x * RPB;

    // ---- load weights / biases into SMEM ----
    for (int i = tid; i < DIMN * HIDN; i += NTHR) W1s[i] = W1[i];
    for (int i = tid; i < HIDN * DIMN; i += NTHR) W2s[i] = W2[i];
    for (int i = tid; i < HIDN; i += NTHR) b1s[i] = b1[i];
    if (tid < DIMN) { b2s[tid] = b2[tid]; wgs[tid] = wg[tid]; }

    // ---- load u (transposed) and emit step-0 output ----
    for (int i = tid; i < RPB * DIMN; i += NTHR) {
        int r = i >> 6, k = i & 63;
        float v = y0[(size_t)(row0 + r) * DIMN + k];
        uT[k * UT_STRIDE + r] = v;
        out[(size_t)(row0 + r) * DIMN + k] = v;
    }

    const float dt  = t[1] - t[0];
    const float bgv = bg[0];
    __syncthreads();

    // ||wg||^2 (every thread computes; trivial, once)
    float Sw = 0.0f;
#pragma unroll
    for (int k = 0; k < DIMN; k++) Sw = fmaf(wgs[k], wgs[k], Sw);

    const int ty = tid >> 5;   // 0..7 -> rows ty*4 .. ty*4+3
    const int tx = tid & 31;   // GEMM1 cols tx*8..+7 ; GEMM2 cols tx*2..+1
    const float* uTp  = uT + ty * 4;
    const float* w1p  = W1s + tx * 8;
    const float* hTp  = hT + ty * 4;
    const float* w2p  = W2s + tx * 2;

    for (int s = 1; s < T; s++) {
        // ================= phase A: GEMM1 + tanh -> hT, and g/coef ========
        float acc[4][8];
#pragma unroll
        for (int i = 0; i < 4; i++)
#pragma unroll
            for (int c = 0; c < 8; c++) acc[i][c] = b1s[tx * 8 + c];

#pragma unroll 4
        for (int k = 0; k < DIMN; k++) {
            float4 a4 = *(const float4*)(uTp + k * UT_STRIDE);    // warp-broadcast
            float4 w0 = *(const float4*)(w1p + k * HIDN);
            float4 w1v = *(const float4*)(w1p + k * HIDN + 4);
            float a[4] = {a4.x, a4.y, a4.z, a4.w};
            float w[8] = {w0.x, w0.y, w0.z, w0.w, w1v.x, w1v.y, w1v.z, w1v.w};
#pragma unroll
            for (int i = 0; i < 4; i++)
#pragma unroll
                for (int c = 0; c < 8; c++)
                    acc[i][c] = fmaf(a[i], w[c], acc[i][c]);
        }
        // tanh + transposed store (stride 36 -> conflict-free STS.128)
#pragma unroll
        for (int c = 0; c < 8; c++) {
            float4 v;
            v.x = fast_tanh(acc[0][c]);
            v.y = fast_tanh(acc[1][c]);
            v.z = fast_tanh(acc[2][c]);
            v.w = fast_tanh(acc[3][c]);
            *(float4*)(hT + (tx * 8 + c) * HT_STRIDE + ty * 4) = v;
        }

        // constraint: 8 threads per row compute u.wg
        {
            int grow = tid >> 3, sub = tid & 7;
            float p = 0.0f;
#pragma unroll
            for (int k8 = 0; k8 < 8; k8++) {
                int k = sub * 8 + k8;
                p = fmaf(uT[k * UT_STRIDE + grow], wgs[k], p);
            }
            p += __shfl_xor_sync(0xffffffffu, p, 4);
            p += __shfl_xor_sync(0xffffffffu, p, 2);
            p += __shfl_xor_sync(0xffffffffu, p, 1);
            if (sub == 0) {
                float g  = fast_tanh(p + bgv);
                float cc = fmaf(-g, g, 1.0f);          // 1 - g^2
                float s2 = cc * cc * Sw;               // |G|^2
                coef[grow] = (fabsf(s2) > EPS_C)
                               ? (GAMMA_C * g / (cc * Sw)) : 0.0f;
            }
        }
        __syncthreads();   // hT + coef ready

        // ================= phase B: GEMM2 + euler update ==================
        float f[4][2];
#pragma unroll
        for (int i = 0; i < 4; i++)
#pragma unroll
            for (int c = 0; c < 2; c++) f[i][c] = b2s[tx * 2 + c];

#pragma unroll 4
        for (int j = 0; j < HIDN; j++) {
            float4 a4 = *(const float4*)(hTp + j * HT_STRIDE);    // warp-broadcast
            float2 w2 = *(const float2*)(w2p + j * DIMN);
            float a[4] = {a4.x, a4.y, a4.z, a4.w};
#pragma unroll
            for (int i = 0; i < 4; i++) {
                f[i][0] = fmaf(a[i], w2.x, f[i][0]);
                f[i][1] = fmaf(a[i], w2.y, f[i][1]);
            }
        }

        float cf[4];
#pragma unroll
        for (int i = 0; i < 4; i++) cf[i] = coef[ty * 4 + i];

        float* outp = out + (size_t)s * BS * DIMN;
#pragma unroll
        for (int c = 0; c < 2; c++) {
            int col = tx * 2 + c;
            float wcol = wgs[col];
#pragma unroll
            for (int i = 0; i < 4; i++) {
                int r = ty * 4 + i;
                float uo = uT[col * UT_STRIDE + r];
                float nv = fmaf(dt, f[i][c] - cf[i] * wcol, uo);
                uT[col * UT_STRIDE + r] = nv;
                outp[(size_t)(row0 + r) * DIMN + col] = nv;
            }
        }
        __syncthreads();   // uT ready for next step; hT free to overwrite
    }
}

extern "C" void kernel_launch(void* const* d_in, const int* in_sizes, int n_in,
                              void* d_out, int out_size)
{
    const float* y0 = (const float*)d_in[0];
    const float* t  = (const float*)d_in[1];
    const float* W1 = (const float*)d_in[2];
    const float* b1 = (const float*)d_in[3];
    const float* W2 = (const float*)d_in[4];
    const float* b2 = (const float*)d_in[5];
    const float* wg = (const float*)d_in[6];
    const float* bg = (const float*)d_in[7];
    float* out = (float*)d_out;

    int BS = in_sizes[0] / DIMN;   // 4096
    int T  = in_sizes[1];          // 101

    cudaFuncSetAttribute(snde_kernel,
                         cudaFuncAttributeMaxDynamicSharedMemorySize, SMEM_BYTES);
    dim3 grid(BS / RPB), block(NTHR);
    snde_kernel<<<grid, block, SMEM_BYTES>>>(y0, t, W1, b1, W2, b2, wg, bg,
                                             out, T, BS);
}

// round 7
// speedup vs baseline: 2.7502x; 2.7502x over previous
#include <cuda_runtime.h>
#include <cuda_fp16.h>
#include <cstdint>

// SNDE via mma.sync (m16n8k16 fp16, fp32 accum), 3-term hi/lo split for
// fp32-class accuracy. tcgen05 unavailable (harness target sm_100, no 'a').
//
// 128 CTAs x 32 rows, 8 warps: warp = (mtile = w&1 -> rows 16*mtile.., nw = w>>1).
// Per step:
//   GEMM1: C1[16,64-slice of 256] = u[16,64] @ W1          (warp n-slice)
//   epi1 : h = tanh(C1 + b1) in-place -> A-frags (reuses u-frag registers)
//   GEMM2: C2[16,64] partial over warp's 64-wide k-slice
//   reduce 4 partials (smem fp32); u += dt*(f + b2 - coef*wg)
//   u stays in C-layout registers -> A-frags for next GEMM1.

#define DIMN 64
#define HIDN 256
#define RPB 32
#define NTHR 256
#define GAMMA_C 0.1f
#define EPS_C 1e-12f

#define W1_STRIDE 264   // halves per k-row (256+8 pad -> conflict-free ldmatrix)
#define W2_STRIDE 72    // halves per k-row (64+8)
#define PART_STRIDE 68  // floats per row

#define SM_W1H 0
#define SM_W1L (SM_W1H + 64*W1_STRIDE*2)       // 33792
#define SM_W2H (SM_W1L + 64*W1_STRIDE*2)       // 67584
#define SM_W2L (SM_W2H + 256*W2_STRIDE*2)      // 104448
#define SM_PART (SM_W2L + 256*W2_STRIDE*2)     // 141312
#define SM_B1 (SM_PART + 8*16*PART_STRIDE*4)   // 176128
#define SM_B2 (SM_B1 + 256*4)
#define SM_WG (SM_B2 + 64*4)
#define SMEM_BYTES (SM_WG + 64*4)              // 177664

static __device__ __forceinline__ uint32_t smem_u32(const void* p) {
    return (uint32_t)__cvta_generic_to_shared(p);
}

static __device__ __forceinline__ void ldsm4t(uint32_t addr, uint32_t& r0,
                                              uint32_t& r1, uint32_t& r2, uint32_t& r3) {
    asm volatile("ldmatrix.sync.aligned.m8n8.x4.trans.shared.b16 {%0,%1,%2,%3}, [%4];"
                 : "=r"(r0), "=r"(r1), "=r"(r2), "=r"(r3) : "r"(addr));
}

static __device__ __forceinline__ void mma16816(float* c, uint32_t a0, uint32_t a1,
                                                uint32_t a2, uint32_t a3,
                                                uint32_t b0, uint32_t b1) {
    asm volatile("mma.sync.aligned.m16n8k16.row.col.f32.f16.f16.f32 "
                 "{%0,%1,%2,%3}, {%4,%5,%6,%7}, {%8,%9}, {%0,%1,%2,%3};"
                 : "+f"(c[0]), "+f"(c[1]), "+f"(c[2]), "+f"(c[3])
                 : "r"(a0), "r"(a1), "r"(a2), "r"(a3), "r"(b0), "r"(b1));
}

// pack (x0 -> low half, x1 -> high half) as fp16 hi; lo = residual pack
static __device__ __forceinline__ void split_pack(float x0, float x1,
                                                  uint32_t& hi, uint32_t& lo) {
    uint32_t ph;
    asm("cvt.rn.f16x2.f32 %0, %1, %2;" : "=r"(ph) : "f"(x1), "f"(x0));
    __half2 h2 = *reinterpret_cast<__half2*>(&ph);
    float r0 = x0 - __low2float(h2);
    float r1 = x1 - __high2float(h2);
    uint32_t pl;
    asm("cvt.rn.f16x2.f32 %0, %1, %2;" : "=r"(pl) : "f"(r1), "f"(r0));
    hi = ph; lo = pl;
}

static __device__ __forceinline__ float tanh_acc(float x) {
    x = fminf(fmaxf(x, -15.0f), 15.0f);
    float e = __expf(2.0f * x);
    return __fdividef(e - 1.0f, e + 1.0f);
}

__global__ __launch_bounds__(NTHR, 1)
void snde_mma_kernel(const float* __restrict__ y0, const float* __restrict__ t,
                     const float* __restrict__ W1, const float* __restrict__ b1,
                     const float* __restrict__ W2, const float* __restrict__ b2,
                     const float* __restrict__ wg, const float* __restrict__ bg,
                     float* __restrict__ out, int T, int BS)
{
    extern __shared__ char smem[];
    const uint32_t sbase = smem_u32(smem);
    const int tid = threadIdx.x;
    const int w = tid >> 5, lane = tid & 31;
    const int mtile = w & 1, nw = w >> 1;       // nw: 64-wide n-slice of GEMM1
    const int g = lane >> 2, tig = lane & 3;    // fragment coords
    const int lrow = lane & 15;                 // ldmatrix x4 row
    const int lcol8 = (lane >> 4) << 3;         // ldmatrix x4 col offset

    float* b1s = (float*)(smem + SM_B1);
    float* b2s = (float*)(smem + SM_B2);
    float* wgs = (float*)(smem + SM_WG);

    // ---- prologue: weights -> fp16 hi/lo padded smem ----
    for (int i = tid; i < DIMN * HIDN; i += NTHR) {          // W1 [64][256]
        int k = i >> 8, n = i & 255;
        float v = W1[i];
        __half h = __float2half_rn(v);
        __half l = __float2half_rn(v - __half2float(h));
        *(__half*)(smem + SM_W1H + (k * W1_STRIDE + n) * 2) = h;
        *(__half*)(smem + SM_W1L + (k * W1_STRIDE + n) * 2) = l;
    }
    for (int i = tid; i < HIDN * DIMN; i += NTHR) {          // W2 [256][64]
        int k = i >> 6, n = i & 63;
        float v = W2[i];
        __half h = __float2half_rn(v);
        __half l = __float2half_rn(v - __half2float(h));
        *(__half*)(smem + SM_W2H + (k * W2_STRIDE + n) * 2) = h;
        *(__half*)(smem + SM_W2L + (k * W2_STRIDE + n) * 2) = l;
    }
    for (int i = tid; i < HIDN; i += NTHR) b1s[i] = b1[i];
    if (tid < DIMN) { b2s[tid] = b2[tid]; wgs[tid] = wg[tid]; }
    __syncthreads();

    float Sw = 0.0f;
#pragma unroll
    for (int k = 0; k < DIMN; k++) Sw = fmaf(wgs[k], wgs[k], Sw);
    const float dtv = t[1] - t[0];
    const float bgv = bg[0];

    // ---- load u in C-fragment layout + step-0 output ----
    const int rowbase = blockIdx.x * RPB + mtile * 16;
    float ur[8][4];
#pragma unroll
    for (int j = 0; j < 8; j++) {
        int c = j * 8 + tig * 2;
        float2 v0 = *(const float2*)(y0 + (size_t)(rowbase + g) * DIMN + c);
        float2 v1 = *(const float2*)(y0 + (size_t)(rowbase + g + 8) * DIMN + c);
        ur[j][0] = v0.x; ur[j][1] = v0.y; ur[j][2] = v1.x; ur[j][3] = v1.y;
    }
    if (nw == 0) {
#pragma unroll
        for (int j = 0; j < 8; j++) {
            int c = j * 8 + tig * 2;
            *(float2*)(out + (size_t)(rowbase + g) * DIMN + c) = make_float2(ur[j][0], ur[j][1]);
            *(float2*)(out + (size_t)(rowbase + g + 8) * DIMN + c) = make_float2(ur[j][2], ur[j][3]);
        }
    }

    // A-fragment registers: hold u-frags during GEMM1, then reused for h-frags
    // in GEMM2 (u-frags are rebuilt from ur at the end of every step).
    uint32_t ah[4][4], al[4][4];
#pragma unroll
    for (int kk = 0; kk < 4; kk++) {
        split_pack(ur[2*kk][0],   ur[2*kk][1],   ah[kk][0], al[kk][0]);
        split_pack(ur[2*kk][2],   ur[2*kk][3],   ah[kk][1], al[kk][1]);
        split_pack(ur[2*kk+1][0], ur[2*kk+1][1], ah[kk][2], al[kk][2]);
        split_pack(ur[2*kk+1][2], ur[2*kk+1][3], ah[kk][3], al[kk][3]);
    }

    const uint32_t part_w = sbase + SM_PART + (uint32_t)(w * 16) * PART_STRIDE * 4;
    const uint32_t part_m = sbase + SM_PART + (uint32_t)(mtile * 16) * PART_STRIDE * 4;

    for (int s = 1; s < T; s++) {
        // ---- constraint coef (warp-local: each warp holds full u rows) ----
        float p0 = 0.0f, p1 = 0.0f;
#pragma unroll
        for (int j = 0; j < 8; j++) {
            float2 wv = *(float2*)(wgs + j * 8 + tig * 2);
            p0 += ur[j][0] * wv.x + ur[j][1] * wv.y;
            p1 += ur[j][2] * wv.x + ur[j][3] * wv.y;
        }
        p0 += __shfl_xor_sync(0xffffffffu, p0, 1); p0 += __shfl_xor_sync(0xffffffffu, p0, 2);
        p1 += __shfl_xor_sync(0xffffffffu, p1, 1); p1 += __shfl_xor_sync(0xffffffffu, p1, 2);
        float g0 = tanh_acc(p0 + bgv), g1 = tanh_acc(p1 + bgv);
        float cc0 = fmaf(-g0, g0, 1.0f), cc1 = fmaf(-g1, g1, 1.0f);
        float coef0 = (fabsf(cc0 * cc0 * Sw) > EPS_C) ? (GAMMA_C * g0 / (cc0 * Sw)) : 0.0f;
        float coef1 = (fabsf(cc1 * cc1 * Sw) > EPS_C) ? (GAMMA_C * g1 / (cc1 * Sw)) : 0.0f;

        // ---- GEMM1: C1[16 x 64-slice] ----
        float C1[8][4];
#pragma unroll
        for (int j = 0; j < 8; j++)
#pragma unroll
            for (int q = 0; q < 4; q++) C1[j][q] = 0.0f;
#pragma unroll
        for (int kk = 0; kk < 4; kk++) {
#pragma unroll
            for (int jp = 0; jp < 4; jp++) {
                uint32_t col = (uint32_t)(nw * 64 + jp * 16 + lcol8);
                uint32_t a1 = sbase + SM_W1H + ((uint32_t)(kk * 16 + lrow) * W1_STRIDE + col) * 2;
                uint32_t a2 = sbase + SM_W1L + ((uint32_t)(kk * 16 + lrow) * W1_STRIDE + col) * 2;
                uint32_t bh0, bh1, bh2, bh3, bl0, bl1, bl2, bl3;
                ldsm4t(a1, bh0, bh1, bh2, bh3);
                ldsm4t(a2, bl0, bl1, bl2, bl3);
                mma16816(C1[2*jp],   ah[kk][0], ah[kk][1], ah[kk][2], ah[kk][3], bh0, bh1);
                mma16816(C1[2*jp],   al[kk][0], al[kk][1], al[kk][2], al[kk][3], bh0, bh1);
                mma16816(C1[2*jp],   ah[kk][0], ah[kk][1], ah[kk][2], ah[kk][3], bl0, bl1);
                mma16816(C1[2*jp+1], ah[kk][0], ah[kk][1], ah[kk][2], ah[kk][3], bh2, bh3);
                mma16816(C1[2*jp+1], al[kk][0], al[kk][1], al[kk][2], al[kk][3], bh2, bh3);
                mma16816(C1[2*jp+1], ah[kk][0], ah[kk][1], ah[kk][2], ah[kk][3], bl2, bl3);
            }
        }

        // ---- epilogue1: h = tanh(C1+b1) in place -> h-frags into ah/al ----
#pragma unroll
        for (int j = 0; j < 8; j++) {
            float2 bv = *(float2*)(b1s + nw * 64 + j * 8 + tig * 2);
            C1[j][0] = tanh_acc(C1[j][0] + bv.x);
            C1[j][1] = tanh_acc(C1[j][1] + bv.y);
            C1[j][2] = tanh_acc(C1[j][2] + bv.x);
            C1[j][3] = tanh_acc(C1[j][3] + bv.y);
        }
#pragma unroll
        for (int jj = 0; jj < 4; jj++) {
            split_pack(C1[2*jj][0],   C1[2*jj][1],   ah[jj][0], al[jj][0]);
            split_pack(C1[2*jj][2],   C1[2*jj][3],   ah[jj][1], al[jj][1]);
            split_pack(C1[2*jj+1][0], C1[2*jj+1][1], ah[jj][2], al[jj][2]);
            split_pack(C1[2*jj+1][2], C1[2*jj+1][3], ah[jj][3], al[jj][3]);
        }

        // ---- GEMM2: partial over k-slice [nw*64, nw*64+64) (reuse C1) ----
#pragma unroll
        for (int j = 0; j < 8; j++)
#pragma unroll
            for (int q = 0; q < 4; q++) C1[j][q] = 0.0f;
#pragma unroll
        for (int jj = 0; jj < 4; jj++) {
            uint32_t k0 = (uint32_t)(nw * 64 + jj * 16 + lrow);
#pragma unroll
            for (int np = 0; np < 4; np++) {
                uint32_t col = (uint32_t)(np * 16 + lcol8);
                uint32_t a1 = sbase + SM_W2H + (k0 * W2_STRIDE + col) * 2;
                uint32_t a2 = sbase + SM_W2L + (k0 * W2_STRIDE + col) * 2;
                uint32_t bh0, bh1, bh2, bh3, bl0, bl1, bl2, bl3;
                ldsm4t(a1, bh0, bh1, bh2, bh3);
                ldsm4t(a2, bl0, bl1, bl2, bl3);
                mma16816(C1[2*np],   ah[jj][0], ah[jj][1], ah[jj][2], ah[jj][3], bh0, bh1);
                mma16816(C1[2*np],   al[jj][0], al[jj][1], al[jj][2], al[jj][3], bh0, bh1);
                mma16816(C1[2*np],   ah[jj][0], ah[jj][1], ah[jj][2], ah[jj][3], bl0, bl1);
                mma16816(C1[2*np+1], ah[jj][0], ah[jj][1], ah[jj][2], ah[jj][3], bh2, bh3);
                mma16816(C1[2*np+1], al[jj][0], al[jj][1], al[jj][2], al[jj][3], bh2, bh3);
                mma16816(C1[2*np+1], ah[jj][0], ah[jj][1], ah[jj][2], ah[jj][3], bl2, bl3);
            }
        }

        // ---- cross-warp reduction of partials over the 4 n-slices ----
#pragma unroll
        for (int j = 0; j < 8; j++) {
            int c = j * 8 + tig * 2;
            *(float2*)(smem + (part_w - sbase) + ((uint32_t)g * PART_STRIDE + c) * 4)
                = make_float2(C1[j][0], C1[j][1]);
            *(float2*)(smem + (part_w - sbase) + ((uint32_t)(g + 8) * PART_STRIDE + c) * 4)
                = make_float2(C1[j][2], C1[j][3]);
        }
        __syncthreads();

        // ---- euler update + output + next A1 fragments ----
        float* o = out + ((size_t)s * BS + rowbase) * DIMN;
#pragma unroll
        for (int j = 0; j < 8; j++) {
            int c = j * 8 + tig * 2;
            float s0 = 0, s1 = 0, s2 = 0, s3 = 0;
#pragma unroll
            for (int sl = 0; sl < 4; sl++) {
                uint32_t pb = (part_m - sbase) + (uint32_t)(sl * 2 * 16) * PART_STRIDE * 4;
                float2 v0 = *(float2*)(smem + pb + ((uint32_t)g * PART_STRIDE + c) * 4);
                float2 v1 = *(float2*)(smem + pb + ((uint32_t)(g + 8) * PART_STRIDE + c) * 4);
                s0 += v0.x; s1 += v0.y; s2 += v1.x; s3 += v1.y;
            }
            float2 wv = *(float2*)(wgs + c);
            float2 bv = *(float2*)(b2s + c);
            ur[j][0] = fmaf(dtv, s0 + bv.x - coef0 * wv.x, ur[j][0]);
            ur[j][1] = fmaf(dtv, s1 + bv.y - coef0 * wv.y, ur[j][1]);
            ur[j][2] = fmaf(dtv, s2 + bv.x - coef1 * wv.x, ur[j][2]);
            ur[j][3] = fmaf(dtv, s3 + bv.y - coef1 * wv.y, ur[j][3]);
            if (nw == 0) {
                *(float2*)(o + (size_t)g * DIMN + c) = make_float2(ur[j][0], ur[j][1]);
                *(float2*)(o + (size_t)(g + 8) * DIMN + c) = make_float2(ur[j][2], ur[j][3]);
            }
        }
#pragma unroll
        for (int kk = 0; kk < 4; kk++) {
            split_pack(ur[2*kk][0],   ur[2*kk][1],   ah[kk][0], al[kk][0]);
            split_pack(ur[2*kk][2],   ur[2*kk][3],   ah[kk][1], al[kk][1]);
            split_pack(ur[2*kk+1][0], ur[2*kk+1][1], ah[kk][2], al[kk][2]);
            split_pack(ur[2*kk+1][2], ur[2*kk+1][3], ah[kk][3], al[kk][3]);
        }
        __syncthreads();   // partial buffer safe to overwrite next step
    }
}

extern "C" void kernel_launch(void* const* d_in, const int* in_sizes, int n_in,
                              void* d_out, int out_size)
{
    const float* y0 = (const float*)d_in[0];
    const float* t  = (const float*)d_in[1];
    const float* W1 = (const float*)d_in[2];
    const float* b1 = (const float*)d_in[3];
    const float* W2 = (const float*)d_in[4];
    const float* b2 = (const float*)d_in[5];
    const float* wg = (const float*)d_in[6];
    const float* bg = (const float*)d_in[7];
    float* out = (float*)d_out;
    int BS = in_sizes[0] / DIMN;   // 4096
    int T  = in_sizes[1];          // 101

    cudaFuncSetAttribute(snde_mma_kernel,
                         cudaFuncAttributeMaxDynamicSharedMemorySize, SMEM_BYTES);
    snde_mma_kernel<<<BS / RPB, NTHR, SMEM_BYTES>>>(y0, t, W1, b1, W2, b2, wg, bg,
                                                    out, T, BS);
}

// round 10
// speedup vs baseline: 2.9340x; 1.0668x over previous
#include <cuda_runtime.h>
#include <cuda_fp16.h>
#include <cstdint>

// SNDE via mma.sync (m16n8k16 fp16, fp32 accum), 3-term hi/lo split.
// R10 = R7-passing kernel + tanh.approx for h (accurate tanh kept for the
// stabilizer g) + interleaved mma accumulators. (W2 register cache from R8
// quarantined pending bisection of repeated container failures.)

#define DIMN 64
#define HIDN 256
#define RPB 32
#define NTHR 256
#define GAMMA_C 0.1f
#define EPS_C 1e-12f

#define W1_STRIDE 264   // halves per k-row (256+8 pad -> conflict-free ldmatrix)
#define W2_STRIDE 72    // halves per k-row (64+8)
#define PART_STRIDE 68  // floats per row

#define SM_W1H 0
#define SM_W1L (SM_W1H + 64*W1_STRIDE*2)       // 33792
#define SM_W2H (SM_W1L + 64*W1_STRIDE*2)       // 67584
#define SM_W2L (SM_W2H + 256*W2_STRIDE*2)      // 104448
#define SM_PART (SM_W2L + 256*W2_STRIDE*2)     // 141312
#define SM_B1 (SM_PART + 8*16*PART_STRIDE*4)   // 176128
#define SM_B2 (SM_B1 + 256*4)
#define SM_WG (SM_B2 + 64*4)
#define SMEM_BYTES (SM_WG + 64*4)              // 177664

static __device__ __forceinline__ uint32_t smem_u32(const void* p) {
    return (uint32_t)__cvta_generic_to_shared(p);
}

static __device__ __forceinline__ void ldsm4t(uint32_t addr, uint32_t& r0,
                                              uint32_t& r1, uint32_t& r2, uint32_t& r3) {
    asm volatile("ldmatrix.sync.aligned.m8n8.x4.trans.shared.b16 {%0,%1,%2,%3}, [%4];"
                 : "=r"(r0), "=r"(r1), "=r"(r2), "=r"(r3) : "r"(addr));
}

static __device__ __forceinline__ void mma16816(float* c, uint32_t a0, uint32_t a1,
                                                uint32_t a2, uint32_t a3,
                                                uint32_t b0, uint32_t b1) {
    asm volatile("mma.sync.aligned.m16n8k16.row.col.f32.f16.f16.f32 "
                 "{%0,%1,%2,%3}, {%4,%5,%6,%7}, {%8,%9}, {%0,%1,%2,%3};"
                 : "+f"(c[0]), "+f"(c[1]), "+f"(c[2]), "+f"(c[3])
                 : "r"(a0), "r"(a1), "r"(a2), "r"(a3), "r"(b0), "r"(b1));
}

// pack (x0 -> low half, x1 -> high half) as fp16 hi; lo = residual pack
static __device__ __forceinline__ void split_pack(float x0, float x1,
                                                  uint32_t& hi, uint32_t& lo) {
    uint32_t ph;
    asm("cvt.rn.f16x2.f32 %0, %1, %2;" : "=r"(ph) : "f"(x1), "f"(x0));
    __half2 h2 = *reinterpret_cast<__half2*>(&ph);
    float r0 = x0 - __low2float(h2);
    float r1 = x1 - __high2float(h2);
    uint32_t pl;
    asm("cvt.rn.f16x2.f32 %0, %1, %2;" : "=r"(pl) : "f"(r1), "f"(r0));
    hi = ph; lo = pl;
}

static __device__ __forceinline__ float tanh_fast(float x) {   // HW tanh (for h)
    float y;
    asm("tanh.approx.f32 %0, %1;" : "=f"(y) : "f"(x));
    return y;
}
static __device__ __forceinline__ float tanh_acc(float x) {    // accurate (for g)
    x = fminf(fmaxf(x, -15.0f), 15.0f);
    float e = __expf(2.0f * x);
    return __fdividef(e - 1.0f, e + 1.0f);
}

__global__ __launch_bounds__(NTHR, 1)
void snde_mma_kernel(const float* __restrict__ y0, const float* __restrict__ t,
                     const float* __restrict__ W1, const float* __restrict__ b1,
                     const float* __restrict__ W2, const float* __restrict__ b2,
                     const float* __restrict__ wg, const float* __restrict__ bg,
                     float* __restrict__ out, int T, int BS)
{
    extern __shared__ char smem[];
    const uint32_t sbase = smem_u32(smem);
    const int tid = threadIdx.x;
    const int w = tid >> 5, lane = tid & 31;
    const int mtile = w & 1, nw = w >> 1;       // nw: 64-wide n-slice of GEMM1
    const int g = lane >> 2, tig = lane & 3;    // fragment coords
    const int lrow = lane & 15;                 // ldmatrix x4 row
    const int lcol8 = (lane >> 4) << 3;         // ldmatrix x4 col offset

    float* b1s = (float*)(smem + SM_B1);
    float* b2s = (float*)(smem + SM_B2);
    float* wgs = (float*)(smem + SM_WG);

    // ---- prologue: weights -> fp16 hi/lo padded smem ----
    for (int i = tid; i < DIMN * HIDN; i += NTHR) {          // W1 [64][256]
        int k = i >> 8, n = i & 255;
        float v = W1[i];
        __half h = __float2half_rn(v);
        __half l = __float2half_rn(v - __half2float(h));
        *(__half*)(smem + SM_W1H + (k * W1_STRIDE + n) * 2) = h;
        *(__half*)(smem + SM_W1L + (k * W1_STRIDE + n) * 2) = l;
    }
    for (int i = tid; i < HIDN * DIMN; i += NTHR) {          // W2 [256][64]
        int k = i >> 6, n = i & 63;
        float v = W2[i];
        __half h = __float2half_rn(v);
        __half l = __float2half_rn(v - __half2float(h));
        *(__half*)(smem + SM_W2H + (k * W2_STRIDE + n) * 2) = h;
        *(__half*)(smem + SM_W2L + (k * W2_STRIDE + n) * 2) = l;
    }
    for (int i = tid; i < HIDN; i += NTHR) b1s[i] = b1[i];
    if (tid < DIMN) { b2s[tid] = b2[tid]; wgs[tid] = wg[tid]; }
    __syncthreads();

    float Sw = 0.0f;
#pragma unroll
    for (int k = 0; k < DIMN; k++) Sw = fmaf(wgs[k], wgs[k], Sw);
    const float dtv = t[1] - t[0];
    const float bgv = bg[0];

    // ---- load u in C-fragment layout + step-0 output ----
    const int rowbase = blockIdx.x * RPB + mtile * 16;
    float ur[8][4];
#pragma unroll
    for (int j = 0; j < 8; j++) {
        int c = j * 8 + tig * 2;
        float2 v0 = *(const float2*)(y0 + (size_t)(rowbase + g) * DIMN + c);
        float2 v1 = *(const float2*)(y0 + (size_t)(rowbase + g + 8) * DIMN + c);
        ur[j][0] = v0.x; ur[j][1] = v0.y; ur[j][2] = v1.x; ur[j][3] = v1.y;
    }
    if (nw == 0) {
#pragma unroll
        for (int j = 0; j < 8; j++) {
            int c = j * 8 + tig * 2;
            *(float2*)(out + (size_t)(rowbase + g) * DIMN + c) = make_float2(ur[j][0], ur[j][1]);
            *(float2*)(out + (size_t)(rowbase + g + 8) * DIMN + c) = make_float2(ur[j][2], ur[j][3]);
        }
    }

    // A-fragment registers: u-frags during GEMM1, reused for h-frags in GEMM2.
    uint32_t ah[4][4], al[4][4];
#pragma unroll
    for (int kk = 0; kk < 4; kk++) {
        split_pack(ur[2*kk][0],   ur[2*kk][1],   ah[kk][0], al[kk][0]);
        split_pack(ur[2*kk][2],   ur[2*kk][3],   ah[kk][1], al[kk][1]);
        split_pack(ur[2*kk+1][0], ur[2*kk+1][1], ah[kk][2], al[kk][2]);
        split_pack(ur[2*kk+1][2], ur[2*kk+1][3], ah[kk][3], al[kk][3]);
    }

    const uint32_t part_w = sbase + SM_PART + (uint32_t)(w * 16) * PART_STRIDE * 4;
    const uint32_t part_m = sbase + SM_PART + (uint32_t)(mtile * 16) * PART_STRIDE * 4;

    for (int s = 1; s < T; s++) {
        // ---- constraint coef (warp-local; accurate tanh) ----
        float p0 = 0.0f, p1 = 0.0f;
#pragma unroll
        for (int j = 0; j < 8; j++) {
            float2 wv = *(float2*)(wgs + j * 8 + tig * 2);
            p0 += ur[j][0] * wv.x + ur[j][1] * wv.y;
            p1 += ur[j][2] * wv.x + ur[j][3] * wv.y;
        }
        p0 += __shfl_xor_sync(0xffffffffu, p0, 1); p0 += __shfl_xor_sync(0xffffffffu, p0, 2);
        p1 += __shfl_xor_sync(0xffffffffu, p1, 1); p1 += __shfl_xor_sync(0xffffffffu, p1, 2);
        float g0 = tanh_acc(p0 + bgv), g1 = tanh_acc(p1 + bgv);
        float cc0 = fmaf(-g0, g0, 1.0f), cc1 = fmaf(-g1, g1, 1.0f);
        float coef0 = (fabsf(cc0 * cc0 * Sw) > EPS_C) ? (GAMMA_C * g0 / (cc0 * Sw)) : 0.0f;
        float coef1 = (fabsf(cc1 * cc1 * Sw) > EPS_C) ? (GAMMA_C * g1 / (cc1 * Sw)) : 0.0f;

        // ---- GEMM1: C1[16 x 64-slice], interleaved accumulators ----
        float C1[8][4];
#pragma unroll
        for (int j = 0; j < 8; j++)
#pragma unroll
            for (int q = 0; q < 4; q++) C1[j][q] = 0.0f;
#pragma unroll
        for (int kk = 0; kk < 4; kk++) {
#pragma unroll
            for (int jp = 0; jp < 4; jp++) {
                uint32_t col = (uint32_t)(nw * 64 + jp * 16 + lcol8);
                uint32_t a1 = sbase + SM_W1H + ((uint32_t)(kk * 16 + lrow) * W1_STRIDE + col) * 2;
                uint32_t a2 = sbase + SM_W1L + ((uint32_t)(kk * 16 + lrow) * W1_STRIDE + col) * 2;
                uint32_t bh0, bh1, bh2, bh3, bl0, bl1, bl2, bl3;
                ldsm4t(a1, bh0, bh1, bh2, bh3);
                ldsm4t(a2, bl0, bl1, bl2, bl3);
                mma16816(C1[2*jp],   ah[kk][0], ah[kk][1], ah[kk][2], ah[kk][3], bh0, bh1);
                mma16816(C1[2*jp+1], ah[kk][0], ah[kk][1], ah[kk][2], ah[kk][3], bh2, bh3);
                mma16816(C1[2*jp],   al[kk][0], al[kk][1], al[kk][2], al[kk][3], bh0, bh1);
                mma16816(C1[2*jp+1], al[kk][0], al[kk][1], al[kk][2], al[kk][3], bh2, bh3);
                mma16816(C1[2*jp],   ah[kk][0], ah[kk][1], ah[kk][2], ah[kk][3], bl0, bl1);
                mma16816(C1[2*jp+1], ah[kk][0], ah[kk][1], ah[kk][2], ah[kk][3], bl2, bl3);
            }
        }

        // ---- epilogue1: h = tanh.approx(C1+b1) in place -> h-frags ----
#pragma unroll
        for (int j = 0; j < 8; j++) {
            float2 bv = *(float2*)(b1s + nw * 64 + j * 8 + tig * 2);
            C1[j][0] = tanh_fast(C1[j][0] + bv.x);
            C1[j][1] = tanh_fast(C1[j][1] + bv.y);
            C1[j][2] = tanh_fast(C1[j][2] + bv.x);
            C1[j][3] = tanh_fast(C1[j][3] + bv.y);
        }
#pragma unroll
        for (int jj = 0; jj < 4; jj++) {
            split_pack(C1[2*jj][0],   C1[2*jj][1],   ah[jj][0], al[jj][0]);
            split_pack(C1[2*jj][2],   C1[2*jj][3],   ah[jj][1], al[jj][1]);
            split_pack(C1[2*jj+1][0], C1[2*jj+1][1], ah[jj][2], al[jj][2]);
            split_pack(C1[2*jj+1][2], C1[2*jj+1][3], ah[jj][3], al[jj][3]);
        }

        // ---- GEMM2: partial over k-slice [nw*64, nw*64+64) (reuse C1) ----
#pragma unroll
        for (int j = 0; j < 8; j++)
#pragma unroll
            for (int q = 0; q < 4; q++) C1[j][q] = 0.0f;
#pragma unroll
        for (int jj = 0; jj < 4; jj++) {
            uint32_t k0 = (uint32_t)(nw * 64 + jj * 16 + lrow);
#pragma unroll
            for (int np = 0; np < 4; np++) {
                uint32_t col = (uint32_t)(np * 16 + lcol8);
                uint32_t a1 = sbase + SM_W2H + (k0 * W2_STRIDE + col) * 2;
                uint32_t a2 = sbase + SM_W2L + (k0 * W2_STRIDE + col) * 2;
                uint32_t bh0, bh1, bh2, bh3, bl0, bl1, bl2, bl3;
                ldsm4t(a1, bh0, bh1, bh2, bh3);
                ldsm4t(a2, bl0, bl1, bl2, bl3);
                mma16816(C1[2*np],   ah[jj][0], ah[jj][1], ah[jj][2], ah[jj][3], bh0, bh1);
                mma16816(C1[2*np+1], ah[jj][0], ah[jj][1], ah[jj][2], ah[jj][3], bh2, bh3);
                mma16816(C1[2*np],   al[jj][0], al[jj][1], al[jj][2], al[jj][3], bh0, bh1);
                mma16816(C1[2*np+1], al[jj][0], al[jj][1], al[jj][2], al[jj][3], bh2, bh3);
                mma16816(C1[2*np],   ah[jj][0], ah[jj][1], ah[jj][2], ah[jj][3], bl0, bl1);
                mma16816(C1[2*np+1], ah[jj][0], ah[jj][1], ah[jj][2], ah[jj][3], bl2, bl3);
            }
        }

        // ---- cross-warp reduction of partials over the 4 n-slices ----
#pragma unroll
        for (int j = 0; j < 8; j++) {
            int c = j * 8 + tig * 2;
            *(float2*)(smem + (part_w - sbase) + ((uint32_t)g * PART_STRIDE + c) * 4)
                = make_float2(C1[j][0], C1[j][1]);
            *(float2*)(smem + (part_w - sbase) + ((uint32_t)(g + 8) * PART_STRIDE + c) * 4)
                = make_float2(C1[j][2], C1[j][3]);
        }
        __syncthreads();

        // ---- euler update + output + next A1 fragments ----
        float* o = out + ((size_t)s * BS + rowbase) * DIMN;
#pragma unroll
        for (int j = 0; j < 8; j++) {
            int c = j * 8 + tig * 2;
            float s0 = 0, s1 = 0, s2 = 0, s3 = 0;
#pragma unroll
            for (int sl = 0; sl < 4; sl++) {
                uint32_t pb = (part_m - sbase) + (uint32_t)(sl * 2 * 16) * PART_STRIDE * 4;
                float2 v0 = *(float2*)(smem + pb + ((uint32_t)g * PART_STRIDE + c) * 4);
                float2 v1 = *(float2*)(smem + pb + ((uint32_t)(g + 8) * PART_STRIDE + c) * 4);
                s0 += v0.x; s1 += v0.y; s2 += v1.x; s3 += v1.y;
            }
            float2 wv = *(float2*)(wgs + c);
            float2 bv = *(float2*)(b2s + c);
            ur[j][0] = fmaf(dtv, s0 + bv.x - coef0 * wv.x, ur[j][0]);
            ur[j][1] = fmaf(dtv, s1 + bv.y - coef0 * wv.y, ur[j][1]);
            ur[j][2] = fmaf(dtv, s2 + bv.x - coef1 * wv.x, ur[j][2]);
            ur[j][3] = fmaf(dtv, s3 + bv.y - coef1 * wv.y, ur[j][3]);
            if (nw == 0) {
                *(float2*)(o + (size_t)g * DIMN + c) = make_float2(ur[j][0], ur[j][1]);
                *(float2*)(o + (size_t)(g + 8) * DIMN + c) = make_float2(ur[j][2], ur[j][3]);
            }
        }
#pragma unroll
        for (int kk = 0; kk < 4; kk++) {
            split_pack(ur[2*kk][0],   ur[2*kk][1],   ah[kk][0], al[kk][0]);
            split_pack(ur[2*kk][2],   ur[2*kk][3],   ah[kk][1], al[kk][1]);
            split_pack(ur[2*kk+1][0], ur[2*kk+1][1], ah[kk][2], al[kk][2]);
            split_pack(ur[2*kk+1][2], ur[2*kk+1][3], ah[kk][3], al[kk][3]);
        }
        __syncthreads();   // partial buffer safe to overwrite next step
    }
}

extern "C" void kernel_launch(void* const* d_in, const int* in_sizes, int n_in,
                              void* d_out, int out_size)
{
    const float* y0 = (const float*)d_in[0];
    const float* t  = (const float*)d_in[1];
    const float* W1 = (const float*)d_in[2];
    const float* b1 = (const float*)d_in[3];
    const float* W2 = (const float*)d_in[4];
    const float* b2 = (const float*)d_in[5];
    const float* wg = (const float*)d_in[6];
    const float* bg = (const float*)d_in[7];
    float* out = (float*)d_out;
    int BS = in_sizes[0] / DIMN;   // 4096
    int T  = in_sizes[1];          // 101

    cudaFuncSetAttribute(snde_mma_kernel,
                         cudaFuncAttributeMaxDynamicSharedMemorySize, SMEM_BYTES);
    snde_mma_kernel<<<BS / RPB, NTHR, SMEM_BYTES>>>(y0, t, W1, b1, W2, b2, wg, bg,
                                                    out, T, BS);
}